// round 3
// baseline (speedup 1.0000x reference)
#include <cuda_runtime.h>
#include <math.h>

#define Bsz 64
#define Ssz 512
#define Hsz 400
#define Dsz 400
#define Vsz 32000
#define Lsz 16
#define NPART 4          // K split
#define KC   100         // K per part
#define JT   24          // j-tile per block

// ---------------- scratch (device globals; no allocation) ----------------
__device__ float g_Gpart[NPART][Bsz][2400];  // [part][b][0:1200 gi | 1200:2400 gh]
__device__ float g_hA[Bsz * Hsz];
__device__ float g_hB[Bsz * Hsz];
__device__ float g_x[Bsz * Dsz];
__device__ float g_scores[Bsz][Ssz];

// ---------------- f32x2 packed-FMA helpers ----------------
__device__ __forceinline__ unsigned long long pk2(float x, float y) {
    unsigned long long r;
    asm("mov.b64 %0, {%1, %2};" : "=l"(r) : "f"(x), "f"(y));
    return r;
}
__device__ __forceinline__ void ffma2(unsigned long long& d,
                                      unsigned long long a, unsigned long long b) {
    asm("fma.rn.f32x2 %0, %1, %2, %0;" : "+l"(d) : "l"(a), "l"(b));
}
__device__ __forceinline__ float2 up2(unsigned long long v) {
    float2 f;
    asm("mov.b64 {%0, %1}, %2;" : "=f"(f.x), "=f"(f.y) : "l"(v));
    return f;
}

// ---------------- zero output with evict-first stores (protect L2 residency of enc) ----
__global__ __launch_bounds__(256) void zero_kernel(float* __restrict__ out, int n4, int n) {
    int idx = blockIdx.x * 256 + threadIdx.x;
    int stride = gridDim.x * 256;
    float4 z = make_float4(0.f, 0.f, 0.f, 0.f);
    for (int i = idx; i < n4; i += stride) {
        float4* p = (float4*)out + i;
        asm volatile("st.global.cs.v4.f32 [%0], {%1, %2, %3, %4};"
                     :: "l"(p), "f"(z.x), "f"(z.y), "f"(z.z), "f"(z.w) : "memory");
    }
    // scalar tail
    for (int i = n4 * 4 + idx; i < n; i += stride) {
        asm volatile("st.global.cs.f32 [%0], %1;" :: "l"(out + i), "f"(0.f) : "memory");
    }
}

// ---------------- init: h0 = encoded_hidden[0], x0 = slot_emb[slot] ----------------
__global__ void init_kernel(const float* __restrict__ eh,
                            const float* __restrict__ slot_emb,
                            const int* __restrict__ slot_p) {
    int idx = blockIdx.x * blockDim.x + threadIdx.x;
    if (idx < Bsz * Hsz) {
        g_hA[idx] = eh[idx];
        int j = idx % Dsz;
        g_x[idx] = slot_emb[slot_p[0] * Dsz + j];
    }
}

// ---------------- K1: GEMM partials ----------------
// grid = 2 mats * 50 jtiles * 4 ksplits = 400 blocks, 96 threads.
// Thread = (tj 0..5, tb 0..15): 4b x 4j micro-tile via fma.rn.f32x2.
__global__ __launch_bounds__(96) void gemm_kernel(const float* __restrict__ Wih,
                                                  const float* __restrict__ Whh,
                                                  int t) {
    __shared__ float As[KC][68];   // [k][b], padded
    __shared__ float Ws[KC][28];   // [k][j], padded

    int bx = blockIdx.x;
    int mat = bx / 200;
    int rem = bx % 200;
    int jt  = rem / NPART;
    int ks  = rem % NPART;
    int jbase = jt * JT;
    int kbase = ks * KC;

    const float* hin = (t & 1) ? g_hB : g_hA;
    const float* A = mat ? hin : g_x;
    const float* W = mat ? Whh : Wih;

    int tid = threadIdx.x;

    for (int i = tid; i < 64 * (KC / 4); i += 96) {   // 1600
        int q = i / 64, b = i % 64;
        float4 v = *(const float4*)&A[b * 400 + kbase + 4 * q];
        As[4 * q + 0][b] = v.x;
        As[4 * q + 1][b] = v.y;
        As[4 * q + 2][b] = v.z;
        As[4 * q + 3][b] = v.w;
    }
    for (int i = tid; i < JT * (KC / 4); i += 96) {   // 600
        int q = i / JT, j = i % JT;
        float4 v = *(const float4*)&W[(jbase + j) * 400 + kbase + 4 * q];
        Ws[4 * q + 0][j] = v.x;
        Ws[4 * q + 1][j] = v.y;
        Ws[4 * q + 2][j] = v.z;
        Ws[4 * q + 3][j] = v.w;
    }
    __syncthreads();

    int tj = tid / 16;          // 0..5
    int tb = tid % 16;          // 0..15
    int b0 = 4 * tb;
    int j0 = 4 * tj;

    unsigned long long acc[4][2];
    #pragma unroll
    for (int jj = 0; jj < 4; jj++) { acc[jj][0] = 0ULL; acc[jj][1] = 0ULL; }

    #pragma unroll 4
    for (int k = 0; k < KC; k++) {
        float4 av = *(const float4*)&As[k][b0];
        float4 wv = *(const float4*)&Ws[k][j0];
        unsigned long long a01 = pk2(av.x, av.y);
        unsigned long long a23 = pk2(av.z, av.w);
        unsigned long long w0 = pk2(wv.x, wv.x);
        unsigned long long w1 = pk2(wv.y, wv.y);
        unsigned long long w2 = pk2(wv.z, wv.z);
        unsigned long long w3 = pk2(wv.w, wv.w);
        ffma2(acc[0][0], a01, w0); ffma2(acc[0][1], a23, w0);
        ffma2(acc[1][0], a01, w1); ffma2(acc[1][1], a23, w1);
        ffma2(acc[2][0], a01, w2); ffma2(acc[2][1], a23, w2);
        ffma2(acc[3][0], a01, w3); ffma2(acc[3][1], a23, w3);
    }

    float val[4][4];
    #pragma unroll
    for (int jj = 0; jj < 4; jj++) {
        float2 lo = up2(acc[jj][0]);
        float2 hi = up2(acc[jj][1]);
        val[jj][0] = lo.x; val[jj][1] = lo.y; val[jj][2] = hi.x; val[jj][3] = hi.y;
    }
    int obase = mat * 1200 + jbase + j0;
    #pragma unroll
    for (int bb = 0; bb < 4; bb++) {
        float4 o = make_float4(val[0][bb], val[1][bb], val[2][bb], val[3][bb]);
        *(float4*)&g_Gpart[ks][b0 + bb][obase] = o;
    }
}

// ---------------- K1.5: gates -> h_new ----------------
__global__ __launch_bounds__(128) void gates_kernel(const float* __restrict__ bih,
                                                    const float* __restrict__ bhh,
                                                    int t) {
    int b = blockIdx.x;
    int tid = threadIdx.x;
    if (tid >= 100) return;
    const float* hin = (t & 1) ? g_hB : g_hA;
    float* hout = (t & 1) ? g_hA : g_hB;

    float4 ir = *(const float4*)&bih[4 * tid];
    float4 iz = *(const float4*)&bih[400 + 4 * tid];
    float4 in_ = *(const float4*)&bih[800 + 4 * tid];
    float4 hr = *(const float4*)&bhh[4 * tid];
    float4 hz = *(const float4*)&bhh[400 + 4 * tid];
    float4 hn = *(const float4*)&bhh[800 + 4 * tid];

    #pragma unroll
    for (int p = 0; p < NPART; p++) {
        const float* P = &g_Gpart[p][b][0];
        float4 v;
        v = *(const float4*)&P[4 * tid];        ir.x += v.x; ir.y += v.y; ir.z += v.z; ir.w += v.w;
        v = *(const float4*)&P[400 + 4 * tid];  iz.x += v.x; iz.y += v.y; iz.z += v.z; iz.w += v.w;
        v = *(const float4*)&P[800 + 4 * tid];  in_.x += v.x; in_.y += v.y; in_.z += v.z; in_.w += v.w;
        v = *(const float4*)&P[1200 + 4 * tid]; hr.x += v.x; hr.y += v.y; hr.z += v.z; hr.w += v.w;
        v = *(const float4*)&P[1600 + 4 * tid]; hz.x += v.x; hz.y += v.y; hz.z += v.z; hz.w += v.w;
        v = *(const float4*)&P[2000 + 4 * tid]; hn.x += v.x; hn.y += v.y; hn.z += v.z; hn.w += v.w;
    }

    float4 hp = *(const float4*)&hin[b * 400 + 4 * tid];
    float4 ho;
    {
        float r = 1.f / (1.f + expf(-(ir.x + hr.x)));
        float z = 1.f / (1.f + expf(-(iz.x + hz.x)));
        float n = tanhf(in_.x + r * hn.x);
        ho.x = (1.f - z) * n + z * hp.x;
    }
    {
        float r = 1.f / (1.f + expf(-(ir.y + hr.y)));
        float z = 1.f / (1.f + expf(-(iz.y + hz.y)));
        float n = tanhf(in_.y + r * hn.y);
        ho.y = (1.f - z) * n + z * hp.y;
    }
    {
        float r = 1.f / (1.f + expf(-(ir.z + hr.z)));
        float z = 1.f / (1.f + expf(-(iz.z + hz.z)));
        float n = tanhf(in_.z + r * hn.z);
        ho.z = (1.f - z) * n + z * hp.z;
    }
    {
        float r = 1.f / (1.f + expf(-(ir.w + hr.w)));
        float z = 1.f / (1.f + expf(-(iz.w + hz.w)));
        float n = tanhf(in_.w + r * hn.w);
        ho.w = (1.f - z) * n + z * hp.w;
    }
    *(float4*)&hout[b * 400 + 4 * tid] = ho;
}

// ---------------- K2: masked scores ----------------
// grid = 64 b * 8 chunks = 512 blocks, 256 threads.
// Each chunk covers 64 s. 4 threads per s; each thread owns a contiguous
// 25-float4 slice -> 25 independent unrolled loads (high MLP).
__global__ __launch_bounds__(256) void score_kernel(const float* __restrict__ enc,
                                                    const int* __restrict__ lens,
                                                    int t) {
    __shared__ float sh[Hsz];
    int bx = blockIdx.x;
    int b = bx >> 3;
    int chunk = bx & 7;
    int tid = threadIdx.x;
    const float* hnew = (t & 1) ? g_hA : g_hB;   // h_out of this step

    if (tid < 100)
        ((float4*)sh)[tid] = ((const float4*)(hnew + b * 400))[tid];
    __syncthreads();

    int len = lens[b];
    int s = chunk * 64 + (tid >> 2);
    int part = tid & 3;

    if (s >= len) {
        if (part == 0) g_scores[b][s] = -INFINITY;
        return;
    }

    const float4* e = (const float4*)(enc + ((size_t)b * Ssz + s) * Hsz) + part * 25;
    const float4* h4 = (const float4*)sh + part * 25;

    float a0 = 0.f, a1 = 0.f, a2 = 0.f, a3 = 0.f;
    #pragma unroll
    for (int q = 0; q < 24; q += 4) {
        float4 e0 = e[q],     h0 = h4[q];
        float4 e1 = e[q + 1], h1 = h4[q + 1];
        float4 e2 = e[q + 2], h2 = h4[q + 2];
        float4 e3 = e[q + 3], h3 = h4[q + 3];
        a0 += e0.x * h0.x; a0 += e0.y * h0.y; a0 += e0.z * h0.z; a0 += e0.w * h0.w;
        a1 += e1.x * h1.x; a1 += e1.y * h1.y; a1 += e1.z * h1.z; a1 += e1.w * h1.w;
        a2 += e2.x * h2.x; a2 += e2.y * h2.y; a2 += e2.z * h2.z; a2 += e2.w * h2.w;
        a3 += e3.x * h3.x; a3 += e3.y * h3.y; a3 += e3.z * h3.z; a3 += e3.w * h3.w;
    }
    {
        float4 e0 = e[24], h0 = h4[24];
        a0 += e0.x * h0.x; a0 += e0.y * h0.y; a0 += e0.z * h0.z; a0 += e0.w * h0.w;
    }
    float acc = (a0 + a1) + (a2 + a3);
    acc += __shfl_xor_sync(0xFFFFFFFFu, acc, 1);
    acc += __shfl_xor_sync(0xFFFFFFFFu, acc, 2);
    if (part == 0) g_scores[b][s] = acc;
}

// ---------------- K3: softmax + scatter + pred + next-x gather ----------------
__global__ __launch_bounds__(512) void softmax_kernel(const int* __restrict__ lens,
                                                      const int* __restrict__ uttrs,
                                                      const int* __restrict__ targets,
                                                      const int* __restrict__ use_tf_p,
                                                      const float* __restrict__ embedding,
                                                      float* __restrict__ out,
                                                      int t, int write_preds) {
    __shared__ float redv[512];
    __shared__ int   redi[512];
    __shared__ int   sh_nxt;

    int b = blockIdx.x;
    int tx = threadIdx.x;

    float myv = g_scores[b][tx];
    redv[tx] = myv;
    redi[tx] = tx;
    __syncthreads();
    // first-index-tie-break max (jnp.argmax semantics)
    for (int st = 256; st > 0; st >>= 1) {
        if (tx < st) {
            float v2 = redv[tx + st];
            int   i2 = redi[tx + st];
            if (v2 > redv[tx] || (v2 == redv[tx] && i2 < redi[tx])) {
                redv[tx] = v2;
                redi[tx] = i2;
            }
        }
        __syncthreads();
    }
    float m = redv[0];
    int amax = redi[0];
    __syncthreads();

    float e = expf(myv - m);     // exp(-inf - m) = 0 for masked rows
    redv[tx] = e;
    __syncthreads();
    for (int st = 256; st > 0; st >>= 1) {
        if (tx < st) redv[tx] += redv[tx + st];
        __syncthreads();
    }
    float sum = redv[0];

    int len = lens[b];
    if (tx < len) {
        float p = e / sum;
        int v = uttrs[b * Ssz + tx];
        atomicAdd(&out[(size_t)b * Lsz * Vsz + (size_t)t * Vsz + v], p);
    }

    if (tx == 0) {
        int pred = uttrs[b * Ssz + amax];
        if (write_preds)
            out[(size_t)Bsz * Lsz * Vsz + (size_t)t * Bsz + b] = (float)pred;
        int tf = use_tf_p[0];
        sh_nxt = tf ? targets[b * Lsz + t] : pred;
    }
    __syncthreads();

    if (tx < 100) {
        ((float4*)(g_x + b * Dsz))[tx] =
            ((const float4*)(embedding + (size_t)sh_nxt * Dsz))[tx];
    }
}

// ---------------- launch ----------------
extern "C" void kernel_launch(void* const* d_in, const int* in_sizes, int n_in,
                              void* d_out, int out_size) {
    const float* eh       = (const float*)d_in[0];   // encoded_hidden (1,B,H)
    const float* enc      = (const float*)d_in[1];   // encoded_outputs (B,S,H)
    const int*   lens     = (const int*)d_in[2];     // encoded_lens (B,)
    const int*   uttrs    = (const int*)d_in[3];     // (B,S)
    const int*   targets  = (const int*)d_in[4];     // (B,L)
    const int*   slot     = (const int*)d_in[5];     // scalar
    const int*   use_tf   = (const int*)d_in[6];     // scalar
    const float* emb      = (const float*)d_in[7];   // (V,D)
    const float* slot_emb = (const float*)d_in[8];   // (NSLOTS,D)
    const float* Wih      = (const float*)d_in[9];   // (3H,D)
    const float* Whh      = (const float*)d_in[10];  // (3H,H)
    const float* bih      = (const float*)d_in[11];
    const float* bhh      = (const float*)d_in[12];
    float* out = (float*)d_out;

    zero_kernel<<<1184, 256>>>(out, out_size / 4, out_size);
    init_kernel<<<50, 512>>>(eh, slot_emb, slot);

    int write_preds = out_size > Bsz * Lsz * Vsz;
    for (int t = 0; t < Lsz; t++) {
        gemm_kernel<<<400, 96>>>(Wih, Whh, t);
        gates_kernel<<<64, 128>>>(bih, bhh, t);
        score_kernel<<<512, 256>>>(enc, lens, t);
        softmax_kernel<<<64, 512>>>(lens, uttrs, targets, use_tf, emb, out, t, write_preds);
    }
}

// round 4
// speedup vs baseline: 1.2870x; 1.2870x over previous
#include <cuda_runtime.h>
#include <math.h>

#define Bsz 64
#define Ssz 512
#define Hsz 400
#define Dsz 400
#define Vsz 32000
#define Lsz 16
#define NPART 4          // K split
#define KC   100         // K per part
#define JT   24          // j-tile per block

// ---------------- scratch (device globals; no allocation) ----------------
__device__ float g_Gpart[NPART][Bsz][2400];  // [part][b][0:1200 gi | 1200:2400 gh]
__device__ float g_hA[Bsz * Hsz];
__device__ float g_hB[Bsz * Hsz];
__device__ float g_x[Bsz * Dsz];
__device__ float g_scores[Bsz][Ssz];
__device__ int   g_cnt[Bsz];                 // zero-initialized; tail resets each step

// ---------------- f32x2 packed-FMA helpers ----------------
__device__ __forceinline__ unsigned long long pk2(float x, float y) {
    unsigned long long r;
    asm("mov.b64 %0, {%1, %2};" : "=l"(r) : "f"(x), "f"(y));
    return r;
}
__device__ __forceinline__ void ffma2(unsigned long long& d,
                                      unsigned long long a, unsigned long long b) {
    asm("fma.rn.f32x2 %0, %1, %2, %0;" : "+l"(d) : "l"(a), "l"(b));
}
__device__ __forceinline__ float2 up2(unsigned long long v) {
    float2 f;
    asm("mov.b64 {%0, %1}, %2;" : "=f"(f.x), "=f"(f.y) : "l"(v));
    return f;
}

// ---------------- zero output with evict-first stores ----------------
__global__ __launch_bounds__(256) void zero_kernel(float* __restrict__ out, int n4, int n) {
    int idx = blockIdx.x * 256 + threadIdx.x;
    int stride = gridDim.x * 256;
    for (int i = idx; i < n4; i += stride) {
        float4* p = (float4*)out + i;
        asm volatile("st.global.cs.v4.f32 [%0], {%1, %2, %3, %4};"
                     :: "l"(p), "f"(0.f), "f"(0.f), "f"(0.f), "f"(0.f) : "memory");
    }
    for (int i = n4 * 4 + idx; i < n; i += stride) {
        asm volatile("st.global.cs.f32 [%0], %1;" :: "l"(out + i), "f"(0.f) : "memory");
    }
}

// ---------------- init ----------------
__global__ void init_kernel(const float* __restrict__ eh,
                            const float* __restrict__ slot_emb,
                            const int* __restrict__ slot_p) {
    int idx = blockIdx.x * blockDim.x + threadIdx.x;
    if (idx < Bsz * Hsz) {
        g_hA[idx] = eh[idx];
        int j = idx % Dsz;
        g_x[idx] = slot_emb[slot_p[0] * Dsz + j];
    }
}

// ---------------- K1: GEMM partials (unchanged from R2 — proven) ----------------
__global__ __launch_bounds__(96) void gemm_kernel(const float* __restrict__ Wih,
                                                  const float* __restrict__ Whh,
                                                  int t) {
    __shared__ float As[KC][68];
    __shared__ float Ws[KC][28];

    int bx = blockIdx.x;
    int mat = bx / 200;
    int rem = bx % 200;
    int jt  = rem / NPART;
    int ks  = rem % NPART;
    int jbase = jt * JT;
    int kbase = ks * KC;

    const float* hin = (t & 1) ? g_hB : g_hA;
    const float* A = mat ? hin : g_x;
    const float* W = mat ? Whh : Wih;

    int tid = threadIdx.x;

    for (int i = tid; i < 64 * (KC / 4); i += 96) {
        int q = i / 64, b = i % 64;
        float4 v = *(const float4*)&A[b * 400 + kbase + 4 * q];
        As[4 * q + 0][b] = v.x;
        As[4 * q + 1][b] = v.y;
        As[4 * q + 2][b] = v.z;
        As[4 * q + 3][b] = v.w;
    }
    for (int i = tid; i < JT * (KC / 4); i += 96) {
        int q = i / JT, j = i % JT;
        float4 v = *(const float4*)&W[(jbase + j) * 400 + kbase + 4 * q];
        Ws[4 * q + 0][j] = v.x;
        Ws[4 * q + 1][j] = v.y;
        Ws[4 * q + 2][j] = v.z;
        Ws[4 * q + 3][j] = v.w;
    }
    __syncthreads();

    int tj = tid / 16;
    int tb = tid % 16;
    int b0 = 4 * tb;
    int j0 = 4 * tj;

    unsigned long long acc[4][2];
    #pragma unroll
    for (int jj = 0; jj < 4; jj++) { acc[jj][0] = 0ULL; acc[jj][1] = 0ULL; }

    #pragma unroll 4
    for (int k = 0; k < KC; k++) {
        float4 av = *(const float4*)&As[k][b0];
        float4 wv = *(const float4*)&Ws[k][j0];
        unsigned long long a01 = pk2(av.x, av.y);
        unsigned long long a23 = pk2(av.z, av.w);
        unsigned long long w0 = pk2(wv.x, wv.x);
        unsigned long long w1 = pk2(wv.y, wv.y);
        unsigned long long w2 = pk2(wv.z, wv.z);
        unsigned long long w3 = pk2(wv.w, wv.w);
        ffma2(acc[0][0], a01, w0); ffma2(acc[0][1], a23, w0);
        ffma2(acc[1][0], a01, w1); ffma2(acc[1][1], a23, w1);
        ffma2(acc[2][0], a01, w2); ffma2(acc[2][1], a23, w2);
        ffma2(acc[3][0], a01, w3); ffma2(acc[3][1], a23, w3);
    }

    float val[4][4];
    #pragma unroll
    for (int jj = 0; jj < 4; jj++) {
        float2 lo = up2(acc[jj][0]);
        float2 hi = up2(acc[jj][1]);
        val[jj][0] = lo.x; val[jj][1] = lo.y; val[jj][2] = hi.x; val[jj][3] = hi.y;
    }
    int obase = mat * 1200 + jbase + j0;
    #pragma unroll
    for (int bb = 0; bb < 4; bb++) {
        float4 o = make_float4(val[0][bb], val[1][bb], val[2][bb], val[3][bb]);
        *(float4*)&g_Gpart[ks][b0 + bb][obase] = o;
    }
}

// ---------------- K2: fused gates + scores + (last block per b) softmax tail ------
// grid = 512 (64 b x 8 chunks of 64 s), 256 threads.
__global__ __launch_bounds__(256) void fused_kernel(const float* __restrict__ enc,
                                                    const int* __restrict__ lens,
                                                    const int* __restrict__ uttrs,
                                                    const int* __restrict__ targets,
                                                    const int* __restrict__ use_tf_p,
                                                    const float* __restrict__ embedding,
                                                    const float* __restrict__ bih,
                                                    const float* __restrict__ bhh,
                                                    float* __restrict__ out,
                                                    int t, int write_preds) {
    __shared__ float sh[Hsz];
    __shared__ float redv[256];
    __shared__ int   redi[256];
    __shared__ int   sh_last;
    __shared__ int   sh_nxt;

    int bx = blockIdx.x;
    int b = bx >> 3;
    int chunk = bx & 7;
    int tid = threadIdx.x;

    const float* hin  = (t & 1) ? g_hB : g_hA;
    float*       hout = (t & 1) ? g_hA : g_hB;

    // ---- gates head: h_new computed redundantly per chunk block (latency overlap) ----
    if (tid < 100) {
        float4 ir = *(const float4*)&bih[4 * tid];
        float4 iz = *(const float4*)&bih[400 + 4 * tid];
        float4 in_ = *(const float4*)&bih[800 + 4 * tid];
        float4 hr = *(const float4*)&bhh[4 * tid];
        float4 hz = *(const float4*)&bhh[400 + 4 * tid];
        float4 hn = *(const float4*)&bhh[800 + 4 * tid];
        #pragma unroll
        for (int p = 0; p < NPART; p++) {
            const float* P = &g_Gpart[p][b][0];
            float4 v;
            v = *(const float4*)&P[4 * tid];        ir.x += v.x; ir.y += v.y; ir.z += v.z; ir.w += v.w;
            v = *(const float4*)&P[400 + 4 * tid];  iz.x += v.x; iz.y += v.y; iz.z += v.z; iz.w += v.w;
            v = *(const float4*)&P[800 + 4 * tid];  in_.x += v.x; in_.y += v.y; in_.z += v.z; in_.w += v.w;
            v = *(const float4*)&P[1200 + 4 * tid]; hr.x += v.x; hr.y += v.y; hr.z += v.z; hr.w += v.w;
            v = *(const float4*)&P[1600 + 4 * tid]; hz.x += v.x; hz.y += v.y; hz.z += v.z; hz.w += v.w;
            v = *(const float4*)&P[2000 + 4 * tid]; hn.x += v.x; hn.y += v.y; hn.z += v.z; hn.w += v.w;
        }
        float4 hp = *(const float4*)&hin[b * 400 + 4 * tid];
        float4 ho;
        {
            float r = 1.f / (1.f + expf(-(ir.x + hr.x)));
            float z = 1.f / (1.f + expf(-(iz.x + hz.x)));
            float n = tanhf(in_.x + r * hn.x);
            ho.x = (1.f - z) * n + z * hp.x;
        }
        {
            float r = 1.f / (1.f + expf(-(ir.y + hr.y)));
            float z = 1.f / (1.f + expf(-(iz.y + hz.y)));
            float n = tanhf(in_.y + r * hn.y);
            ho.y = (1.f - z) * n + z * hp.y;
        }
        {
            float r = 1.f / (1.f + expf(-(ir.z + hr.z)));
            float z = 1.f / (1.f + expf(-(iz.z + hz.z)));
            float n = tanhf(in_.z + r * hn.z);
            ho.z = (1.f - z) * n + z * hp.z;
        }
        {
            float r = 1.f / (1.f + expf(-(ir.w + hr.w)));
            float z = 1.f / (1.f + expf(-(iz.w + hz.w)));
            float n = tanhf(in_.w + r * hn.w);
            ho.w = (1.f - z) * n + z * hp.w;
        }
        *(float4*)&sh[4 * tid] = ho;
        if (chunk == 0)
            *(float4*)&hout[b * 400 + 4 * tid] = ho;   // for next step's GEMM
    }
    __syncthreads();

    // ---- masked dot scores: warp per s, lane-strided coalesced loads, 2-s interleave ----
    int len = lens[b];
    int warp = tid >> 5, lane = tid & 31;
    int sbase = chunk * 64 + warp * 8;
    const float4* h4 = (const float4*)sh;

    for (int i = 0; i < 8; i += 2) {
        int s0 = sbase + i;
        int s1 = s0 + 1;
        bool v0 = s0 < len, v1 = s1 < len;
        float acc0 = 0.f, acc1 = 0.f;
        if (v0 | v1) {
            const float4* e0 = (const float4*)(enc + ((size_t)b * Ssz + s0) * Hsz);
            const float4* e1 = (const float4*)(enc + ((size_t)b * Ssz + s1) * Hsz);
            float4 h0 = h4[lane], h1 = h4[lane + 32], h2 = h4[lane + 64];
            if (v0) {
                float4 a = e0[lane];
                float4 c = e0[lane + 32];
                float4 d = e0[lane + 64];
                acc0 += a.x * h0.x; acc0 += a.y * h0.y; acc0 += a.z * h0.z; acc0 += a.w * h0.w;
                acc0 += c.x * h1.x; acc0 += c.y * h1.y; acc0 += c.z * h1.z; acc0 += c.w * h1.w;
                acc0 += d.x * h2.x; acc0 += d.y * h2.y; acc0 += d.z * h2.z; acc0 += d.w * h2.w;
            }
            if (v1) {
                float4 a = e1[lane];
                float4 c = e1[lane + 32];
                float4 d = e1[lane + 64];
                acc1 += a.x * h0.x; acc1 += a.y * h0.y; acc1 += a.z * h0.z; acc1 += a.w * h0.w;
                acc1 += c.x * h1.x; acc1 += c.y * h1.y; acc1 += c.z * h1.z; acc1 += c.w * h1.w;
                acc1 += d.x * h2.x; acc1 += d.y * h2.y; acc1 += d.z * h2.z; acc1 += d.w * h2.w;
            }
            if (lane < 4) {
                float4 h3 = h4[96 + lane];
                if (v0) {
                    float4 a = e0[96 + lane];
                    acc0 += a.x * h3.x; acc0 += a.y * h3.y; acc0 += a.z * h3.z; acc0 += a.w * h3.w;
                }
                if (v1) {
                    float4 a = e1[96 + lane];
                    acc1 += a.x * h3.x; acc1 += a.y * h3.y; acc1 += a.z * h3.z; acc1 += a.w * h3.w;
                }
            }
            #pragma unroll
            for (int off = 16; off; off >>= 1) {
                acc0 += __shfl_xor_sync(0xFFFFFFFFu, acc0, off);
                acc1 += __shfl_xor_sync(0xFFFFFFFFu, acc1, off);
            }
        }
        if (lane == 0) {
            g_scores[b][s0] = v0 ? acc0 : -INFINITY;
            g_scores[b][s1] = v1 ? acc1 : -INFINITY;
        }
    }

    // ---- last-block-per-b becomes the softmax tail ----
    __threadfence();
    __syncthreads();
    if (tid == 0) {
        int old = atomicAdd(&g_cnt[b], 1);
        sh_last = (old == 7);
    }
    __syncthreads();
    if (!sh_last) return;
    __threadfence();                    // acquire: make peers' score writes visible
    if (tid == 0) g_cnt[b] = 0;         // reset for next step

    float v0 = g_scores[b][tid];
    float v1 = g_scores[b][tid + 256];
    // pair combine, first-index tie-break (jnp.argmax semantics)
    float mv; int mi;
    if (v1 > v0) { mv = v1; mi = tid + 256; } else { mv = v0; mi = tid; }
    redv[tid] = mv;
    redi[tid] = mi;
    __syncthreads();
    for (int st = 128; st > 0; st >>= 1) {
        if (tid < st) {
            float w2 = redv[tid + st];
            int   i2 = redi[tid + st];
            if (w2 > redv[tid] || (w2 == redv[tid] && i2 < redi[tid])) {
                redv[tid] = w2;
                redi[tid] = i2;
            }
        }
        __syncthreads();
    }
    float m = redv[0];
    int amax = redi[0];
    __syncthreads();

    float e0 = expf(v0 - m);
    float e1 = expf(v1 - m);
    redv[tid] = e0 + e1;
    __syncthreads();
    for (int st = 128; st > 0; st >>= 1) {
        if (tid < st) redv[tid] += redv[tid + st];
        __syncthreads();
    }
    float inv = 1.f / redv[0];

    float* orow = out + (size_t)b * Lsz * Vsz + (size_t)t * Vsz;
    if (tid < len)
        atomicAdd(&orow[uttrs[b * Ssz + tid]], e0 * inv);
    if (tid + 256 < len)
        atomicAdd(&orow[uttrs[b * Ssz + tid + 256]], e1 * inv);

    if (tid == 0) {
        int pred = uttrs[b * Ssz + amax];
        if (write_preds)
            out[(size_t)Bsz * Lsz * Vsz + (size_t)t * Bsz + b] = (float)pred;
        sh_nxt = use_tf_p[0] ? targets[b * Lsz + t] : pred;
    }
    __syncthreads();

    if (tid < 100) {
        ((float4*)(g_x + b * Dsz))[tid] =
            ((const float4*)(embedding + (size_t)sh_nxt * Dsz))[tid];
    }
}

// ---------------- launch ----------------
extern "C" void kernel_launch(void* const* d_in, const int* in_sizes, int n_in,
                              void* d_out, int out_size) {
    const float* eh       = (const float*)d_in[0];
    const float* enc      = (const float*)d_in[1];
    const int*   lens     = (const int*)d_in[2];
    const int*   uttrs    = (const int*)d_in[3];
    const int*   targets  = (const int*)d_in[4];
    const int*   slot     = (const int*)d_in[5];
    const int*   use_tf   = (const int*)d_in[6];
    const float* emb      = (const float*)d_in[7];
    const float* slot_emb = (const float*)d_in[8];
    const float* Wih      = (const float*)d_in[9];
    const float* Whh      = (const float*)d_in[10];
    const float* bih      = (const float*)d_in[11];
    const float* bhh      = (const float*)d_in[12];
    float* out = (float*)d_out;

    zero_kernel<<<1184, 256>>>(out, out_size / 4, out_size);
    init_kernel<<<50, 512>>>(eh, slot_emb, slot);

    int write_preds = out_size > Bsz * Lsz * Vsz;
    for (int t = 0; t < Lsz; t++) {
        gemm_kernel<<<400, 96>>>(Wih, Whh, t);
        fused_kernel<<<512, 256>>>(enc, lens, uttrs, targets, use_tf, emb,
                                   bih, bhh, out, t, write_preds);
    }
}